// round 5
// baseline (speedup 1.0000x reference)
#include <cuda_runtime.h>
#include <cuda_fp16.h>
#include <cstdint>

// ---- SMEM layout (bytes): 7 x 32KB unpadded swizzled fp16 tiles + small ----
#define OFF_OUTA 0
#define OFF_OUTB 32768
#define OFF_HA   65536
#define OFF_HB   98304
#define OFF_WIM  131072
#define OFF_W1   163840
#define OFF_W2   196608
#define OFF_C0   229376   // float2 (wz,bi)[128] = 1KB ; ALIASED as sO2 float[256]
#define OFF_WF   230400   // float[128]
#define OFF_B12  230912   // float2 (b1,b2)[128] = 1KB
#define SMEM_TOTAL 231936

// ---- device scratch ----
__device__ __half g_WiM[(size_t)128 * 16384];  // per-i swizzled 128x128 fp16 image
__device__ float  g_wz[128 * 128];
__device__ __half g_W1h[16384];                // swizzled image
__device__ __half g_W2h[16384];
__device__ float  g_zT[(size_t)128 * 131072];  // [i][b]

// XOR-swizzled byte offset in a 128x128 fp16 tile (row = 256B)
__host__ __device__ __forceinline__ uint32_t tile_off(int r, int c) {
    return (uint32_t)(r * 256 + ((c * 2) ^ ((r & 7) << 4)));
}

// ---- prologue kernels ----
__global__ void prep_weights(const float* __restrict__ Wi, const float* __restrict__ M,
                             const float* __restrict__ W1, const float* __restrict__ W2) {
    int i = blockIdx.x;
    if (i < 128) {
        const float* Wii = Wi + (size_t)i * 16512;   // 128*129
        for (int v = threadIdx.x; v < 16384; v += blockDim.x) {
            int j = v >> 7, k = v & 127;
            float m = (k == i) ? 0.f : M[k * 128 + i];
            g_WiM[(size_t)i * 16384 + (tile_off(j, k) >> 1)] = __float2half(Wii[j * 129 + k] * m);
        }
        for (int j = threadIdx.x; j < 128; j += blockDim.x)
            g_wz[i * 128 + j] = Wii[j * 129 + 128];
    } else if (i == 128) {
        for (int v = threadIdx.x; v < 16384; v += blockDim.x)
            g_W1h[tile_off(v >> 7, v & 127) >> 1] = __float2half(W1[v]);
    } else {
        for (int v = threadIdx.x; v < 16384; v += blockDim.x)
            g_W2h[tile_off(v >> 7, v & 127) >> 1] = __float2half(W2[v]);
    }
}

__global__ void transpose_z(const float* __restrict__ z, int Bn) {
    __shared__ float t[32][33];
    int b0 = blockIdx.x * 32, i0 = blockIdx.y * 32;
    #pragma unroll
    for (int r = threadIdx.y; r < 32; r += 8)
        t[r][threadIdx.x] = z[(size_t)(b0 + r) * 128 + i0 + threadIdx.x];
    __syncthreads();
    #pragma unroll
    for (int r = threadIdx.y; r < 32; r += 8)
        g_zT[(size_t)(i0 + r) * Bn + b0 + threadIdx.x] = t[threadIdx.x][r];
}

// ---- mma helpers ----
__device__ __forceinline__ void ldsm4(uint32_t addr, uint32_t* r) {
    asm volatile("ldmatrix.sync.aligned.m8n8.x4.shared.b16 {%0,%1,%2,%3},[%4];"
        : "=r"(r[0]), "=r"(r[1]), "=r"(r[2]), "=r"(r[3]) : "r"(addr));
}
// fp16-accumulate mma: D(2 x f16x2) = A*B + D
__device__ __forceinline__ void mma16816h(uint32_t* d, const uint32_t* a, const uint32_t* b) {
    asm volatile("mma.sync.aligned.m16n8k16.row.col.f16.f16.f16.f16 "
        "{%0,%1},{%2,%3,%4,%5},{%6,%7},{%0,%1};"
        : "+r"(d[0]), "+r"(d[1])
        : "r"(a[0]), "r"(a[1]), "r"(a[2]), "r"(a[3]), "r"(b[0]), "r"(b[1]));
}
__device__ __forceinline__ void cpa16(uint32_t s, const void* g) {
    asm volatile("cp.async.cg.shared.global [%0],[%1],16;" :: "r"(s), "l"(g));
}
// combine two fp16 split-K chains -> 4 fp32 values {r0c0, r0c1, r1c0, r1c1}
__device__ __forceinline__ void comb4(const uint32_t* P, const uint32_t* Q, float* v) {
    float2 p0 = __half22float2(*(const __half2*)&P[0]);
    float2 p1 = __half22float2(*(const __half2*)&P[1]);
    float2 q0 = __half22float2(*(const __half2*)&Q[0]);
    float2 q1 = __half22float2(*(const __half2*)&Q[1]);
    v[0] = p0.x + q0.x; v[1] = p0.y + q0.y; v[2] = p1.x + q1.x; v[3] = p1.y + q1.y;
}

// dual-tile GEMM, fp16 accumulate, split-K (chain 0: k0..63, chain 1: k64..127).
// accX[chain][mt][nt][2] fp16x2 regs. B loaded once per kstep, shared across tiles.
__device__ __forceinline__ void gemm2x(uint32_t aBaseA, uint32_t aBaseB, uint32_t bBase,
                                       int lane, int mrow, int ncol,
                                       uint32_t accA[2][2][8][2], uint32_t accB[2][2][8][2]) {
    #pragma unroll
    for (int h = 0; h < 2; h++)
        #pragma unroll
        for (int mt = 0; mt < 2; mt++)
            #pragma unroll
            for (int nt = 0; nt < 8; nt++) {
                accA[h][mt][nt][0] = 0u; accA[h][mt][nt][1] = 0u;
                accB[h][mt][nt][0] = 0u; accB[h][mt][nt][1] = 0u;
            }

    const int rA = mrow + (lane & 15);
    const uint32_t rowA0 = aBaseA + (uint32_t)(rA * 256);
    const uint32_t rowB0 = aBaseB + (uint32_t)(rA * 256);
    const uint32_t xorA = (uint32_t)((rA & 7) << 4);
    const uint32_t cA = (lane & 16) ? 16u : 0u;
    const int rB = ncol + (lane & 7) + ((lane & 16) ? 8 : 0);
    const uint32_t rowW = bBase + (uint32_t)(rB * 256);
    const uint32_t xorB = (uint32_t)((lane & 7) << 4);
    const uint32_t cB = (lane & 8) ? 16u : 0u;

    #pragma unroll
    for (int ks = 0; ks < 8; ks++) {
        const int h = ks >> 2;                    // split-K chain index
        uint32_t offA = ((uint32_t)(ks * 32) + cA) ^ xorA;
        uint32_t offB = ((uint32_t)(ks * 32) + cB) ^ xorB;
        uint32_t a0[4], a1[4], c0[4], c1[4], b[16];
        ldsm4(rowA0 + offA, a0);
        ldsm4(rowA0 + 4096 + offA, a1);
        ldsm4(rowB0 + offA, c0);
        ldsm4(rowB0 + 4096 + offA, c1);
        #pragma unroll
        for (int q = 0; q < 4; q++) ldsm4(rowW + (uint32_t)(q * 4096) + offB, b + 4 * q);
        #pragma unroll
        for (int nt = 0; nt < 8; nt++) {
            const uint32_t* bb = b + (nt >> 1) * 4 + (nt & 1) * 2;
            mma16816h(accA[h][0][nt], a0, bb);
            mma16816h(accA[h][1][nt], a1, bb);
            mma16816h(accB[h][0][nt], c0, bb);
            mma16816h(accB[h][1][nt], c1, bb);
        }
    }
}

// ---- main kernel: 1 CTA = 2 batch tiles of 128, fp16-acc legacy HMMA ----
__global__ __launch_bounds__(256, 1)
void gen_main(const float* __restrict__ x,  const float* __restrict__ bi,
              const float* __restrict__ Wf, const float* __restrict__ bf,
              const float* __restrict__ b1, const float* __restrict__ b2,
              float* __restrict__ out, int Bn)
{
    extern __shared__ char sm[];
    const int tid = threadIdx.x, lane = tid & 31, wid = tid >> 5;
    const int wm = wid >> 1, wn = wid & 1;
    const int mrow = wm * 32, ncol = wn * 64;
    const int gr0 = lane >> 2, gc0 = 2 * (lane & 3);
    const size_t b0 = (size_t)blockIdx.x * 256;

    const uint32_t smBase = (uint32_t)__cvta_generic_to_shared(sm);
    const uint32_t aOutA = smBase + OFF_OUTA, aOutB = smBase + OFF_OUTB;
    const uint32_t aHA = smBase + OFF_HA, aHB = smBase + OFF_HB;
    const uint32_t aWiM = smBase + OFF_WIM, aW1 = smBase + OFF_W1, aW2 = smBase + OFF_W2;
    float2* sC0  = (float2*)(sm + OFF_C0);
    float*  sO2  = (float*)(sm + OFF_C0);      // alias; disjoint lifetime within step
    float*  sWf  = (float*)(sm + OFF_WF);
    float2* sB12 = (float2*)(sm + OFF_B12);

    // ---- stage x into both tiles (fp16, swizzled) ----
    const float4* xg = (const float4*)(x + b0 * 128);
    #pragma unroll
    for (int q = 0; q < 32; q++) {
        int v = (q << 8) + tid;
        float4 f = xg[v];
        int rv = v >> 5, c4 = (v & 31) << 2;
        uint32_t off = tile_off(rv & 127, c4);
        char* base = sm + ((rv >> 7) ? OFF_OUTB : OFF_OUTA);
        *(__half2*)(base + off)     = __floats2half2_rn(f.x, f.y);
        *(__half2*)(base + off + 4) = __floats2half2_rn(f.z, f.w);
    }
    // ---- stage W1/W2 (pre-swizzled) + WiM(0) ----
    #pragma unroll
    for (int q = 0; q < 8; q++) {
        int v = (q << 8) + tid;
        ((uint4*)(sm + OFF_W1))[v] = ((const uint4*)g_W1h)[v];
        ((uint4*)(sm + OFF_W2))[v] = ((const uint4*)g_W2h)[v];
        cpa16(aWiM + (uint32_t)(v << 4), ((const uint4*)g_WiM) + v);
    }
    asm volatile("cp.async.commit_group;");
    if (tid < 128) sB12[tid] = make_float2(b1[tid], b2[tid]);
    asm volatile("cp.async.wait_group 0;");
    __syncthreads();

    uint32_t accA[2][2][8][2], accB[2][2][8][2];

    for (int i = 0; i < 128; i++) {
        if (tid < 128) {
            sC0[tid] = make_float2(g_wz[(i << 7) + tid], bi[(i << 7) + tid]);
            sWf[tid] = Wf[(i << 7) + tid];
        }
        const float bfi = bf[i];
        const float* zg = g_zT + (size_t)i * Bn + b0;
        __syncthreads();

        // ---- G0 pair: h1_pre = out @ WiM^T ----
        gemm2x(aOutA, aOutB, aWiM, lane, mrow, ncol, accA, accB);
        __syncthreads();                         // all WiM reads done
        if (i < 127) {                           // prefetch WiM(i+1)
            const uint4* src = (const uint4*)(g_WiM + (size_t)(i + 1) * 16384);
            #pragma unroll
            for (int q = 0; q < 8; q++) {
                int v = (q << 8) + tid;
                cpa16(aWiM + (uint32_t)(v << 4), src + v);
            }
            asm volatile("cp.async.commit_group;");
        }
        // ---- E0 pair: h1 = relu(pre + z*wz + bi) -> sHA/sHB ----
        #pragma unroll
        for (int t = 0; t < 2; t++) {
            uint32_t (*acc)[2][8][2] = t ? accB : accA;
            const uint32_t hB = t ? aHB : aHA;
            const float* zt = zg + (t << 7);
            #pragma unroll
            for (int mt = 0; mt < 2; mt++) {
                int r0 = mrow + mt * 16 + gr0, r1 = r0 + 8;
                float z0 = zt[r0], z1 = zt[r1];
                uint32_t row0 = hB + (uint32_t)(r0 * 256), row1 = hB + (uint32_t)(r1 * 256);
                uint32_t xr = (uint32_t)((r0 & 7) << 4);
                #pragma unroll
                for (int nt = 0; nt < 8; nt++) {
                    int c = ncol + nt * 8 + gc0;
                    float2 a0 = sC0[c], a1 = sC0[c + 1];
                    float v[4];
                    comb4(acc[0][mt][nt], acc[1][mt][nt], v);
                    float v00 = fmaxf(fmaf(z0, a0.x, v[0]) + a0.y, 0.f);
                    float v01 = fmaxf(fmaf(z0, a1.x, v[1]) + a1.y, 0.f);
                    float v10 = fmaxf(fmaf(z1, a0.x, v[2]) + a0.y, 0.f);
                    float v11 = fmaxf(fmaf(z1, a1.x, v[3]) + a1.y, 0.f);
                    uint32_t cb = ((uint32_t)(2 * c)) ^ xr;
                    *(__half2*)(sm + (row0 + cb - smBase)) = __floats2half2_rn(v00, v01);
                    *(__half2*)(sm + (row1 + cb - smBase)) = __floats2half2_rn(v10, v11);
                }
            }
        }
        __syncthreads();

        // ---- G1 pair: h2_pre = h1 @ W1^T ----
        gemm2x(aHA, aHB, aW1, lane, mrow, ncol, accA, accB);
        __syncthreads();
        // ---- E1 pair: h2 = relu(pre + b1) in place ----
        #pragma unroll
        for (int t = 0; t < 2; t++) {
            uint32_t (*acc)[2][8][2] = t ? accB : accA;
            const uint32_t hB = t ? aHB : aHA;
            #pragma unroll
            for (int mt = 0; mt < 2; mt++) {
                int r0 = mrow + mt * 16 + gr0, r1 = r0 + 8;
                uint32_t row0 = hB + (uint32_t)(r0 * 256), row1 = hB + (uint32_t)(r1 * 256);
                uint32_t xr = (uint32_t)((r0 & 7) << 4);
                #pragma unroll
                for (int nt = 0; nt < 8; nt++) {
                    int c = ncol + nt * 8 + gc0;
                    float q0 = sB12[c].x, q1 = sB12[c + 1].x;
                    float v[4];
                    comb4(acc[0][mt][nt], acc[1][mt][nt], v);
                    float v00 = fmaxf(v[0] + q0, 0.f);
                    float v01 = fmaxf(v[1] + q1, 0.f);
                    float v10 = fmaxf(v[2] + q0, 0.f);
                    float v11 = fmaxf(v[3] + q1, 0.f);
                    uint32_t cb = ((uint32_t)(2 * c)) ^ xr;
                    *(__half2*)(sm + (row0 + cb - smBase)) = __floats2half2_rn(v00, v01);
                    *(__half2*)(sm + (row1 + cb - smBase)) = __floats2half2_rn(v10, v11);
                }
            }
        }
        __syncthreads();

        // ---- G2 pair: h3_pre = h2 @ W2^T ----
        gemm2x(aHA, aHB, aW2, lane, mrow, ncol, accA, accB);

        // ---- E2: o = relu(pre + b2) @ Wf + bf ; write col i ----
        #pragma unroll
        for (int t = 0; t < 2; t++) {
            uint32_t (*acc)[2][8][2] = t ? accB : accA;
            float p[2][2] = {{0.f, 0.f}, {0.f, 0.f}};
            #pragma unroll
            for (int mt = 0; mt < 2; mt++)
                #pragma unroll
                for (int nt = 0; nt < 8; nt++) {
                    int c = ncol + nt * 8 + gc0;
                    float wf0 = sWf[c], wf1 = sWf[c + 1];
                    float q0 = sB12[c].y, q1 = sB12[c + 1].y;
                    float v[4];
                    comb4(acc[0][mt][nt], acc[1][mt][nt], v);
                    p[mt][0] = fmaf(fmaxf(v[0] + q0, 0.f), wf0,
                               fmaf(fmaxf(v[1] + q1, 0.f), wf1, p[mt][0]));
                    p[mt][1] = fmaf(fmaxf(v[2] + q0, 0.f), wf0,
                               fmaf(fmaxf(v[3] + q1, 0.f), wf1, p[mt][1]));
                }
            __syncthreads();                     // sO2 free (prev use done)
            #pragma unroll
            for (int mt = 0; mt < 2; mt++)
                #pragma unroll
                for (int h = 0; h < 2; h++) {
                    float v = p[mt][h];
                    v += __shfl_xor_sync(0xffffffffu, v, 1);
                    v += __shfl_xor_sync(0xffffffffu, v, 2);
                    if ((lane & 3) == 0)
                        sO2[wn * 128 + mrow + mt * 16 + h * 8 + gr0] = v;
                }
            __syncthreads();
            if (tid < 128) {
                float o = sO2[tid] + sO2[128 + tid] + bfi;
                out[(b0 + (size_t)(t << 7) + tid) * 128 + i] = o;
                char* base = sm + (t ? OFF_OUTB : OFF_OUTA);
                *(__half*)(base + tile_off(tid, i)) = __float2half(o);
            }
        }
        if (i < 127) asm volatile("cp.async.wait_group 0;");
        __syncthreads();
    }
}

// ---- host ----
extern "C" void kernel_launch(void* const* d_in, const int* in_sizes, int n_in,
                              void* d_out, int out_size) {
    const float* x  = (const float*)d_in[0];
    const float* z  = (const float*)d_in[1];
    const float* M  = (const float*)d_in[2];
    const float* Wi = (const float*)d_in[3];
    const float* bi = (const float*)d_in[4];
    const float* Wf = (const float*)d_in[5];
    const float* bf = (const float*)d_in[6];
    const float* W1 = (const float*)d_in[7];
    const float* b1 = (const float*)d_in[8];
    const float* W2 = (const float*)d_in[9];
    const float* b2 = (const float*)d_in[10];
    int Bn = in_sizes[0] / 128;

    cudaFuncSetAttribute(gen_main, cudaFuncAttributeMaxDynamicSharedMemorySize, SMEM_TOTAL);

    prep_weights<<<130, 256>>>(Wi, M, W1, W2);
    transpose_z<<<dim3(Bn / 32, 4), dim3(32, 8)>>>(z, Bn);
    gen_main<<<Bn / 256, 256, SMEM_TOTAL>>>(x, bi, Wf, bf, b1, b2, (float*)d_out, Bn);
}